// round 1
// baseline (speedup 1.0000x reference)
#include <cuda_runtime.h>
#include <cstdint>

#define BS 2
#define NF 16
#define C  32
#define H  128
#define W  128
#define HW (H*W)
#define NM 8
#define NK 3
#define MID (NF/2)
#define CHUNK 1024
#define NCH (HW/CHUNK)

typedef unsigned long long ull;

// Scratch partials: [b][c][m][f][chunk] — fully overwritten every launch (deterministic).
__device__ float g_part[BS*C*NM*NF*NCH];

// ---------------------------------------------------------------------------
// Kernel A: masks[b,m,h,w] = sum_c dec[b,MID,c,h,w] * seg_w[m,c] + seg_b[m]
// 256 threads, 1 pixel/thread. grid = (HW/256, BS)
// ---------------------------------------------------------------------------
__global__ void masks_kernel(const float* __restrict__ dec,
                             const float* __restrict__ seg_w,
                             const float* __restrict__ seg_b,
                             float* __restrict__ masks_out)
{
    __shared__ float sw[NM*C];
    __shared__ float sb[NM];
    int tid = threadIdx.x;
    if (tid < NM*C) sw[tid] = seg_w[tid];
    if (tid < NM)   sb[tid] = seg_b[tid];
    __syncthreads();

    int b = blockIdx.y;
    int p = blockIdx.x * blockDim.x + tid;

    const float* src = dec + ((size_t)(b*NF + MID))*C*HW + p;

    float acc[NM];
#pragma unroll
    for (int m = 0; m < NM; m++) acc[m] = sb[m];

#pragma unroll
    for (int c = 0; c < C; c++) {
        float v = src[(size_t)c*HW];
#pragma unroll
        for (int m = 0; m < NM; m++) acc[m] += v * sw[m*C + c];
    }

#pragma unroll
    for (int m = 0; m < NM; m++)
        masks_out[((size_t)b*NM + m)*HW + p] = acc[m];
}

// ---------------------------------------------------------------------------
// Kernel B: partial[b,c,m,f,ch] = sum_{p in chunk} dec[b,f,c,p] * masks[b,m,p]
// grid = (NCH, NF, BS), 256 threads = 8 warps, warp owns 4 channels.
// Mask tile staged in smem (32 KB). Packed fma.rn.f32x2 on pixel pairs.
// ---------------------------------------------------------------------------
__global__ void __launch_bounds__(256, 2)
pool_kernel(const float* __restrict__ dec, const float* __restrict__ masks)
{
    __shared__ float smask[NM*CHUNK];   // 32 KB

    const int b   = blockIdx.z;
    const int f   = blockIdx.y;
    const int ch  = blockIdx.x;
    const int tid = threadIdx.x;

    // Stage masks[b, 0..7, ch*CHUNK : (ch+1)*CHUNK] as float4
    {
        const float* msrc = masks + (size_t)b*NM*HW + (size_t)ch*CHUNK;
        for (int k = tid; k < NM*CHUNK/4; k += 256) {
            int m  = k / (CHUNK/4);
            int i4 = k % (CHUNK/4);
            reinterpret_cast<float4*>(smask)[m*(CHUNK/4) + i4] =
                reinterpret_cast<const float4*>(msrc + (size_t)m*HW)[i4];
        }
    }
    __syncthreads();

    const int wid  = tid >> 5;
    const int lane = tid & 31;

    // Warp wid handles channels [4*wid, 4*wid+3]
    const float* base = dec + (((size_t)(b*NF + f))*C + wid*4)*HW + (size_t)ch*CHUNK;

    ull acc[4][NM];
#pragma unroll
    for (int j = 0; j < 4; j++)
#pragma unroll
        for (int m = 0; m < NM; m++) acc[j][m] = 0ULL;

    // Pixel pairs: CHUNK/2 = 512 pairs, 16 iterations per lane.
#pragma unroll 2
    for (int i = lane; i < CHUNK/2; i += 32) {
        ull mk[NM];
#pragma unroll
        for (int m = 0; m < NM; m++)
            mk[m] = reinterpret_cast<const ull*>(smask + m*CHUNK)[i];

#pragma unroll
        for (int j = 0; j < 4; j++) {
            ull v = reinterpret_cast<const ull*>(base + (size_t)j*HW)[i];
#pragma unroll
            for (int m = 0; m < NM; m++)
                asm("fma.rn.f32x2 %0, %1, %2, %0;"
                    : "+l"(acc[j][m]) : "l"(v), "l"(mk[m]));
        }
    }

    // Reduce: pack-halves add, then warp butterfly; lane 0 writes partial.
#pragma unroll
    for (int j = 0; j < 4; j++) {
#pragma unroll
        for (int m = 0; m < NM; m++) {
            float2 a = *reinterpret_cast<float2*>(&acc[j][m]);
            float s = a.x + a.y;
#pragma unroll
            for (int off = 16; off; off >>= 1)
                s += __shfl_xor_sync(0xffffffffu, s, off);
            if (lane == 0) {
                int c = wid*4 + j;
                g_part[((((size_t)b*C + c)*NM + m)*NF + f)*NCH + ch] = s;
            }
        }
    }
}

// ---------------------------------------------------------------------------
// Kernel C: pooled[b,m,c] = mean_f sum_ch partial ; logits = pooled @ lw^T + lb
// grid = (NM, BS), 128 threads.
// ---------------------------------------------------------------------------
__global__ void logits_kernel(const float* __restrict__ lw,
                              const float* __restrict__ lb,
                              float* __restrict__ out)
{
    const int b = blockIdx.y, m = blockIdx.x;
    const int tid = threadIdx.x;          // 128 threads
    __shared__ float pooled[C];
    __shared__ float partial[128];

    int c = tid >> 2;    // 0..31
    int g = tid & 3;     // 0..3
    const float* src = g_part + (((size_t)b*C + c)*NM + m)*NF*NCH;
    float s = 0.f;
    for (int i = g; i < NF*NCH; i += 4) s += src[i];
    partial[tid] = s;
    __syncthreads();

    if (g == 0)
        pooled[c] = (partial[tid] + partial[tid+1] + partial[tid+2] + partial[tid+3])
                    * (1.0f / NF);
    __syncthreads();

    if (tid < NK) {
        float acc = lb[tid];
#pragma unroll
        for (int c2 = 0; c2 < C; c2++) acc += pooled[c2] * lw[tid*C + c2];
        out[(size_t)b*(NM*NK) + m*NK + tid] = acc;
    }
}

// ---------------------------------------------------------------------------
extern "C" void kernel_launch(void* const* d_in, const int* in_sizes, int n_in,
                              void* d_out, int out_size)
{
    const float* dec   = (const float*)d_in[0];
    const float* seg_w = (const float*)d_in[1];
    const float* seg_b = (const float*)d_in[2];
    const float* lw    = (const float*)d_in[3];
    const float* lb    = (const float*)d_in[4];

    float* out    = (float*)d_out;
    float* logits = out;                 // 48 floats
    float* masks  = out + BS*NM*NK;      // 262144 floats

    masks_kernel <<<dim3(HW/256, BS), 256>>>(dec, seg_w, seg_b, masks);
    pool_kernel  <<<dim3(NCH, NF, BS), 256>>>(dec, masks);
    logits_kernel<<<dim3(NM, BS), 128>>>(lw, lb, logits);
}

// round 2
// speedup vs baseline: 1.1892x; 1.1892x over previous
#include <cuda_runtime.h>
#include <cstdint>

#define BS 2
#define NF 16
#define C  32
#define H  128
#define W  128
#define HW (H*W)
#define NM 8
#define NK 3
#define MID (NF/2)
#define CHUNK 64
#define NCH (HW/CHUNK)     // 256

typedef unsigned long long ull;

// Scratch partials: [b][c][m][ch] — every element written exactly once per launch.
__device__ float g_part[BS*C*NM*NCH];   // 512 KB

// ---------------------------------------------------------------------------
// Fused kernel: per (b, chunk) block of 512 threads (16 warps)
//   Phase 1: stage mid-frame chunk (32ch x 64px) to smem (coalesced float4)
//   Phase 2: compute masks tile (8 x 64) -> smem + gmem output
//   Phase 3: pool all 16 frames, warp owns 2 channels, f32x2 FMAs,
//            accumulate across frames in registers
//   Phase 4: warp butterfly reduce, write partials
// ---------------------------------------------------------------------------
__global__ void __launch_bounds__(512, 1)
fused_kernel(const float* __restrict__ dec,
             const float* __restrict__ seg_w,
             const float* __restrict__ seg_b,
             float* __restrict__ masks_out)
{
    __shared__ float sdec[C*CHUNK];    // 8 KB  mid-frame chunk
    __shared__ float smask[NM*CHUNK];  // 2 KB  mask tile
    __shared__ float sw[NM*C];         // 1 KB
    __shared__ float sb[NM];

    const int tid = threadIdx.x;
    const int ch  = blockIdx.x;
    const int b   = blockIdx.y;

    if (tid < NM*C) sw[tid] = seg_w[tid];
    if (tid < NM)   sb[tid] = seg_b[tid];

    // ---- Phase 1: load mid-frame chunk, one float4 per thread ----
    {
        const int c  = tid >> 4;        // 0..31
        const int q4 = tid & 15;        // 0..15 (16 float4 per 64-px row)
        const float* src = dec + (((size_t)(b*NF + MID))*C + c)*HW
                               + (size_t)ch*CHUNK + q4*4;
        float4 v = *reinterpret_cast<const float4*>(src);
        *reinterpret_cast<float4*>(sdec + c*CHUNK + q4*4) = v;
    }
    __syncthreads();

    // ---- Phase 2: masks[m, px] for this chunk ----
    {
        const int m  = tid >> 6;        // 0..7
        const int px = tid & 63;        // 0..63
        float a = sb[m];
#pragma unroll
        for (int c = 0; c < C; c++)
            a += sdec[c*CHUNK + px] * sw[m*C + c];
        smask[m*CHUNK + px] = a;
        masks_out[((size_t)b*NM + m)*HW + (size_t)ch*CHUNK + px] = a;
    }
    __syncthreads();

    // ---- Phase 3: pooling. warp w -> channels {2w, 2w+1}; lane -> pixel pair ----
    const int wid  = tid >> 5;          // 0..15
    const int lane = tid & 31;
    const int c0   = wid * 2;

    ull mk[NM];
#pragma unroll
    for (int m = 0; m < NM; m++)
        mk[m] = *reinterpret_cast<const ull*>(smask + m*CHUNK + 2*lane);

    ull acc[2][NM];
#pragma unroll
    for (int j = 0; j < 2; j++)
#pragma unroll
        for (int m = 0; m < NM; m++) acc[j][m] = 0ULL;

    const float* fbase = dec + ((size_t)b*NF*C + c0)*HW + (size_t)ch*CHUNK;

#pragma unroll 4
    for (int f = 0; f < NF; f++) {
        const ull* p = reinterpret_cast<const ull*>(fbase + (size_t)f*C*HW);
        ull v0 = p[lane];               // channel c0, pair "lane"
        ull v1 = p[HW/2 + lane];        // channel c0+1
#pragma unroll
        for (int m = 0; m < NM; m++) {
            asm("fma.rn.f32x2 %0, %1, %2, %0;" : "+l"(acc[0][m]) : "l"(v0), "l"(mk[m]));
            asm("fma.rn.f32x2 %0, %1, %2, %0;" : "+l"(acc[1][m]) : "l"(v1), "l"(mk[m]));
        }
    }

    // ---- Phase 4: reduce per (channel, mask) across the warp ----
#pragma unroll
    for (int j = 0; j < 2; j++) {
#pragma unroll
        for (int m = 0; m < NM; m++) {
            float2 a = *reinterpret_cast<float2*>(&acc[j][m]);
            float s = a.x + a.y;
#pragma unroll
            for (int off = 16; off; off >>= 1)
                s += __shfl_xor_sync(0xffffffffu, s, off);
            if (lane == 0) {
                int c = c0 + j;
                g_part[(((size_t)b*C + c)*NM + m)*NCH + ch] = s;
            }
        }
    }
}

// ---------------------------------------------------------------------------
// Logits kernel: pooled[b,m,c] = (sum_ch part)/NF ; logits = pooled @ lw^T + lb
// grid (NM, BS), 256 threads.
// ---------------------------------------------------------------------------
__global__ void logits_kernel(const float* __restrict__ lw,
                              const float* __restrict__ lb,
                              float* __restrict__ out)
{
    const int b = blockIdx.y, m = blockIdx.x;
    const int tid = threadIdx.x;            // 256
    __shared__ float pooled[C];
    __shared__ float partial[256];

    const int c = tid >> 3;                 // 0..31
    const int g = tid & 7;                  // 0..7
    const float* src = g_part + (((size_t)b*C + c)*NM + m)*NCH;
    float s = 0.f;
#pragma unroll 8
    for (int i = g; i < NCH; i += 8) s += src[i];
    partial[tid] = s;
    __syncthreads();

    if (g == 0) {
        float t = 0.f;
#pragma unroll
        for (int k = 0; k < 8; k++) t += partial[tid + k];
        pooled[c] = t * (1.0f / NF);
    }
    __syncthreads();

    if (tid < NK) {
        float acc = lb[tid];
#pragma unroll
        for (int c2 = 0; c2 < C; c2++) acc += pooled[c2] * lw[tid*C + c2];
        out[(size_t)b*(NM*NK) + m*NK + tid] = acc;
    }
}

// ---------------------------------------------------------------------------
extern "C" void kernel_launch(void* const* d_in, const int* in_sizes, int n_in,
                              void* d_out, int out_size)
{
    const float* dec   = (const float*)d_in[0];
    const float* seg_w = (const float*)d_in[1];
    const float* seg_b = (const float*)d_in[2];
    const float* lw    = (const float*)d_in[3];
    const float* lb    = (const float*)d_in[4];

    float* out    = (float*)d_out;
    float* logits = out;                 // 48 floats
    float* masks  = out + BS*NM*NK;      // 262144 floats

    fused_kernel <<<dim3(NCH, BS), 512>>>(dec, seg_w, seg_b, masks);
    logits_kernel<<<dim3(NM, BS), 256>>>(lw, lb, logits);
}